// round 9
// baseline (speedup 1.0000x reference)
#include <cuda_runtime.h>
#include <cuda_fp16.h>
#include <cstdint>

// Problem constants
#define NN   50000
#define EE   800000
#define NIN  128
#define NHID 256
#define XV4  (NN * NIN / 4)     // 1.6M float4 in x

// ---------------- scratch (no allocations allowed) ----------------
__device__ int    g_deg[NN];                  // edge-only degree (zeroed via memset)
__device__ float  g_dinv[NN];
__device__ int    g_ptr[NN + 1];
__device__ int    g_cur[NN];
__device__ int    g_src[EE];
__device__ __half g_xh [(size_t)NN * NIN];    // x in fp16 (agg input)
__device__ __half g_hh [(size_t)NN * NIN];    // aggregated features, fp16
__device__ __half g_h1h[(size_t)NN * NHID];   // hidden layer, fp16
__device__ __half g_w0t[NHID * NIN];          // W0^T [n][k] fp16
__device__ __half g_w1t[NHID * NHID];         // W1^T [n][k] fp16

// ---------------- per-thread edge dtype probe ----------------
// int32 data read as int64 gives values >= 2^32 unless hi word is 0
// (p ~ 2e-5 per probe for node ids < 50000); 4 probes -> negligible.
// Reads are identical across threads -> L1 broadcast hits.
__device__ __forceinline__ int probe_is64(const void* __restrict__ ei) {
    const long long* p = (const long long*)ei;
    int ok = 1;
    #pragma unroll
    for (int t = 0; t < 4; t++) {
        long long v = __ldg(&p[t]);
        ok &= (v >= 0 && v < NN) ? 1 : 0;
    }
    return ok;
}

// ---------------- prep: x->fp16 + W transpose + edge degree count ----------------
__global__ void k_prep(const float* __restrict__ x, const void* __restrict__ ei,
                       const float* __restrict__ W0, const float* __restrict__ W1) {
    int i = blockIdx.x * blockDim.x + threadIdx.x;
    if (i < XV4) {
        float4 v = ((const float4*)x)[i];
        __half2 h0 = __floats2half2_rn(v.x, v.y);
        __half2 h1 = __floats2half2_rn(v.z, v.w);
        uint2 u;
        u.x = *(uint32_t*)&h0;
        u.y = *(uint32_t*)&h1;
        ((uint2*)g_xh)[i] = u;
    }
    if (i < NHID * NIN) {           // W0^T: i = n*128 + k
        int n = i >> 7, k = i & 127;
        g_w0t[i] = __float2half_rn(W0[k * NHID + n]);
    }
    if (i < NHID * NHID) {          // W1^T: i = n*256 + k
        int n = i >> 8, k = i & 255;
        g_w1t[i] = __float2half_rn(W1[k * NHID + n]);
    }
    if (i < EE / 4) {               // degree count, 4 edges/thread
        int e4 = 4 * i;
        int c0, c1, c2, c3;
        if (probe_is64(ei)) {
            const longlong2* p = (const longlong2*)((const long long*)ei + EE + e4);
            longlong2 a = p[0], b = p[1];
            c0 = (int)a.x; c1 = (int)a.y; c2 = (int)b.x; c3 = (int)b.y;
        } else {
            int4 v = *(const int4*)((const int*)ei + EE + e4);
            c0 = v.x; c1 = v.y; c2 = v.z; c3 = v.w;
        }
        atomicAdd(&g_deg[c0], 1);
        atomicAdd(&g_deg[c1], 1);
        atomicAdd(&g_deg[c2], 1);
        atomicAdd(&g_deg[c3], 1);
    }
}

// ---------------- single-block scan: deg -> ptr/cur, dinv ----------------
#define SCT 1024
#define SCH ((NN + SCT - 1) / SCT)   // 49 elements per thread
__global__ void __launch_bounds__(SCT) k_scan() {
    __shared__ int sh[SCT];
    int t = threadIdx.x;
    int start = t * SCH;
    int end   = min(start + SCH, NN);
    int sum = 0;
    for (int i = start; i < end; i++) {
        int d = g_deg[i];
        g_dinv[i] = rsqrtf((float)(d + 1));   // +1 self loop
        sum += d;
    }
    sh[t] = sum;
    __syncthreads();
    for (int off = 1; off < SCT; off <<= 1) {
        int v = (t >= off) ? sh[t - off] : 0;
        __syncthreads();
        sh[t] += v;
        __syncthreads();
    }
    int acc = sh[t] - sum;   // exclusive prefix of this thread's chunk
    for (int i = start; i < end; i++) {
        g_ptr[i] = acc;
        g_cur[i] = acc;
        acc += g_deg[i];
    }
    if (t == 0) g_ptr[NN] = EE;
}

// ---------------- fill CSR (4 edges / thread) ----------------
__global__ void k_fill(const void* __restrict__ ei) {
    int e4 = 4 * (blockIdx.x * blockDim.x + threadIdx.x);
    if (e4 >= EE) return;
    int r0, r1, r2, r3, c0, c1, c2, c3;
    if (probe_is64(ei)) {
        const longlong2* pr = (const longlong2*)((const long long*)ei + e4);
        const longlong2* pc = (const longlong2*)((const long long*)ei + EE + e4);
        longlong2 a = pr[0], b = pr[1], c = pc[0], d = pc[1];
        r0 = (int)a.x; r1 = (int)a.y; r2 = (int)b.x; r3 = (int)b.y;
        c0 = (int)c.x; c1 = (int)c.y; c2 = (int)d.x; c3 = (int)d.y;
    } else {
        int4 a = *(const int4*)((const int*)ei + e4);
        int4 b = *(const int4*)((const int*)ei + EE + e4);
        r0 = a.x; r1 = a.y; r2 = a.z; r3 = a.w;
        c0 = b.x; c1 = b.y; c2 = b.z; c3 = b.w;
    }
    g_src[atomicAdd(&g_cur[c0], 1)] = r0;
    g_src[atomicAdd(&g_cur[c1], 1)] = r1;
    g_src[atomicAdd(&g_cur[c2], 1)] = r2;
    g_src[atomicAdd(&g_cur[c3], 1)] = r3;
}

// ---------------- aggregation: warp per target node, fp16 in/out ----------------
__global__ void __launch_bounds__(256) k_agg() {
    int w = (blockIdx.x * blockDim.x + threadIdx.x) >> 5;
    int lane = threadIdx.x & 31;
    if (w >= NN) return;
    float di = g_dinv[w];
    const uint2* __restrict__ xh = (const uint2*)g_xh;   // 32 uint2 per row

    uint2 raw = xh[(size_t)w * 32 + lane];               // self loop
    float2 s0 = __half22float2(*(const __half2*)&raw.x);
    float2 s1 = __half22float2(*(const __half2*)&raw.y);
    float4 a;
    a.x = di * s0.x; a.y = di * s0.y; a.z = di * s1.x; a.w = di * s1.y;

    int s = g_ptr[w], e = g_ptr[w + 1];
    #pragma unroll 2
    for (int k = s; k < e; k++) {
        int   j  = __ldg(&g_src[k]);
        float wj = __ldg(&g_dinv[j]);
        uint2 r  = xh[(size_t)j * 32 + lane];
        float2 v0 = __half22float2(*(const __half2*)&r.x);
        float2 v1 = __half22float2(*(const __half2*)&r.y);
        a.x = fmaf(wj, v0.x, a.x);
        a.y = fmaf(wj, v0.y, a.y);
        a.z = fmaf(wj, v1.x, a.z);
        a.w = fmaf(wj, v1.y, a.w);
    }
    a.x *= di; a.y *= di; a.z *= di; a.w *= di;
    __half2 o0 = __floats2half2_rn(a.x, a.y);
    __half2 o1 = __floats2half2_rn(a.z, a.w);
    uint2 u;
    u.x = *(uint32_t*)&o0;
    u.y = *(uint32_t*)&o1;
    ((uint2*)g_hh)[(size_t)w * 32 + lane] = u;
}

// ---------------- FP16 tensor-core GEMM + ReLU, cp.async double-buffered ----------------
// Block tile 128x128, K-slab 64, 8 warps (2M x 4N), warp tile 64x32.
#define AST 36                      // smem row stride in words; 144B = 9*16B aligned
#define SLAB_W (128 * AST)          // words per slab buffer
#define SMEM_GEMM (4 * SLAB_W * 4)  // A0,A1,B0,B1 in bytes (73728)

__device__ __forceinline__ void cp16(uint32_t dst_smem, const void* src, int sz) {
    asm volatile("cp.async.cg.shared.global [%0], [%1], 16, %2;\n"
                 :: "r"(dst_smem), "l"(src), "r"(sz));
}
__device__ __forceinline__ void cp_commit() {
    asm volatile("cp.async.commit_group;\n");
}
template<int N>
__device__ __forceinline__ void cp_wait() {
    asm volatile("cp.async.wait_group %0;\n" :: "n"(N));
}

__device__ __forceinline__ void mma_fp16(float& d0, float& d1, float& d2, float& d3,
                                         uint32_t a0, uint32_t a1, uint32_t a2, uint32_t a3,
                                         uint32_t b0, uint32_t b1) {
    asm volatile(
        "mma.sync.aligned.m16n8k16.row.col.f32.f16.f16.f32 "
        "{%0,%1,%2,%3}, {%4,%5,%6,%7}, {%8,%9}, {%0,%1,%2,%3};"
        : "+f"(d0), "+f"(d1), "+f"(d2), "+f"(d3)
        : "r"(a0), "r"(a1), "r"(a2), "r"(a3), "r"(b0), "r"(b1));
}

// LAYER 1: A = g_hh (K=128), WT = g_w0t, C = g_h1h (fp16)
// LAYER 2: A = g_h1h (K=256), WT = g_w1t, C = Cout (fp32)
template<int K, int LAYER>
__global__ void __launch_bounds__(256) gemm_fp16(float* __restrict__ Cout, int M) {
    const __half* __restrict__ A  = (LAYER == 1) ? g_hh : g_h1h;
    const __half* __restrict__ WT = (LAYER == 1) ? g_w0t : g_w1t;

    extern __shared__ uint32_t smem[];
    uint32_t* Abuf[2] = { smem,             smem + SLAB_W };
    uint32_t* Bbuf[2] = { smem + 2*SLAB_W,  smem + 3*SLAB_W };

    int tid  = threadIdx.x;
    int lane = tid & 31;
    int wid  = tid >> 5;
    int wM = (wid >> 2) * 64;
    int wN = (wid & 3) * 32;
    int r4 = lane >> 2;
    int c4 = lane & 3;

    int brow = blockIdx.x * 128;
    int bcol = blockIdx.y * 128;

    // async load of one 64-k slab into buffer b (A: rows may be OOB -> zfill)
    auto load_slab = [&](int b, int k0) {
        uint32_t a_base = (uint32_t)__cvta_generic_to_shared(Abuf[b]);
        uint32_t b_base = (uint32_t)__cvta_generic_to_shared(Bbuf[b]);
        #pragma unroll
        for (int t = 0; t < 4; t++) {
            int idx = tid + t * 256;        // uint4 index, 8 per row
            int row = idx >> 3;
            int c   = idx & 7;
            int grow = brow + row;
            int ok = (grow < M);
            const __half* srcA = A + (size_t)(ok ? grow : 0) * K + k0 + c * 8;
            cp16(a_base + (row * AST + c * 4) * 4, srcA, ok ? 16 : 0);
            const __half* srcB = WT + (size_t)(bcol + row) * K + k0 + c * 8;
            cp16(b_base + (row * AST + c * 4) * 4, srcB, 16);
        }
        cp_commit();
    };

    float acc[4][4][4];
    #pragma unroll
    for (int mt = 0; mt < 4; mt++)
        #pragma unroll
        for (int nt = 0; nt < 4; nt++)
            #pragma unroll
            for (int r = 0; r < 4; r++) acc[mt][nt][r] = 0.f;

    const int NSLAB = K / 64;
    load_slab(0, 0);

    #pragma unroll
    for (int i = 0; i < NSLAB; i++) {
        if (i + 1 < NSLAB) {
            load_slab((i + 1) & 1, (i + 1) * 64);
            cp_wait<1>();
        } else {
            cp_wait<0>();
        }
        __syncthreads();

        const uint32_t* As = Abuf[i & 1];
        const uint32_t* Bs = Bbuf[i & 1];
        #pragma unroll
        for (int s = 0; s < 4; s++) {      // 4 x k16 steps
            int kw = s * 8;
            uint32_t af[4][4];
            #pragma unroll
            for (int mt = 0; mt < 4; mt++) {
                int r = wM + mt * 16 + r4;
                af[mt][0] = As[r * AST + c4 + kw];
                af[mt][1] = As[(r + 8) * AST + c4 + kw];
                af[mt][2] = As[r * AST + c4 + 4 + kw];
                af[mt][3] = As[(r + 8) * AST + c4 + 4 + kw];
            }
            uint32_t bf[4][2];
            #pragma unroll
            for (int nt = 0; nt < 4; nt++) {
                int n = wN + nt * 8 + r4;
                bf[nt][0] = Bs[n * AST + c4 + kw];
                bf[nt][1] = Bs[n * AST + c4 + 4 + kw];
            }
            #pragma unroll
            for (int mt = 0; mt < 4; mt++)
                #pragma unroll
                for (int nt = 0; nt < 4; nt++)
                    mma_fp16(acc[mt][nt][0], acc[mt][nt][1], acc[mt][nt][2], acc[mt][nt][3],
                             af[mt][0], af[mt][1], af[mt][2], af[mt][3],
                             bf[nt][0], bf[nt][1]);
        }
        __syncthreads();   // all reads of this buffer done before it is re-filled
    }

    // epilogue
    #pragma unroll
    for (int mt = 0; mt < 4; mt++) {
        int row0 = brow + wM + mt * 16 + r4;
        #pragma unroll
        for (int nt = 0; nt < 4; nt++) {
            int col = bcol + wN + nt * 8 + c4 * 2;
            if (LAYER == 1) {
                if (row0 < M) {
                    __half2 h = __floats2half2_rn(fmaxf(acc[mt][nt][0], 0.f),
                                                  fmaxf(acc[mt][nt][1], 0.f));
                    *(__half2*)(g_h1h + (size_t)row0 * NHID + col) = h;
                }
                if (row0 + 8 < M) {
                    __half2 h = __floats2half2_rn(fmaxf(acc[mt][nt][2], 0.f),
                                                  fmaxf(acc[mt][nt][3], 0.f));
                    *(__half2*)(g_h1h + (size_t)(row0 + 8) * NHID + col) = h;
                }
            } else {
                if (row0 < M) {
                    float2 v;
                    v.x = fmaxf(acc[mt][nt][0], 0.f);
                    v.y = fmaxf(acc[mt][nt][1], 0.f);
                    *(float2*)(Cout + (size_t)row0 * NHID + col) = v;
                }
                if (row0 + 8 < M) {
                    float2 v;
                    v.x = fmaxf(acc[mt][nt][2], 0.f);
                    v.y = fmaxf(acc[mt][nt][3], 0.f);
                    *(float2*)(Cout + (size_t)(row0 + 8) * NHID + col) = v;
                }
            }
        }
    }
}

extern "C" void kernel_launch(void* const* d_in, const int* in_sizes, int n_in,
                              void* d_out, int out_size) {
    const float* x  = nullptr;
    const float* W0 = nullptr;
    const float* W1 = nullptr;
    const void*  ei = nullptr;
    for (int i = 0; i < n_in; i++) {
        long long sz = in_sizes[i];
        if      (sz == (long long)NN * NIN)    x  = (const float*)d_in[i];
        else if (sz == (long long)NIN * NHID)  W0 = (const float*)d_in[i];
        else if (sz == (long long)NHID * NHID) W1 = (const float*)d_in[i];
        else if (sz == (long long)2 * EE)      ei = d_in[i];
    }

    void* deg_ptr = nullptr;
    cudaGetSymbolAddress(&deg_ptr, g_deg);
    cudaMemsetAsync(deg_ptr, 0, NN * sizeof(int));

    cudaFuncSetAttribute(gemm_fp16<NIN, 1>,
                         cudaFuncAttributeMaxDynamicSharedMemorySize, SMEM_GEMM);
    cudaFuncSetAttribute(gemm_fp16<NHID, 2>,
                         cudaFuncAttributeMaxDynamicSharedMemorySize, SMEM_GEMM);

    k_prep<<<(XV4 + 255) / 256, 256>>>(x, ei, W0, W1);
    k_scan<<<1, SCT>>>();
    k_fill<<<(EE / 4 + 255) / 256, 256>>>(ei);
    k_agg <<<(NN * 32 + 255) / 256, 256>>>();

    dim3 gg((NN + 127) / 128, NHID / 128);
    gemm_fp16<NIN,  1><<<gg, 256, SMEM_GEMM>>>(nullptr, NN);        // g_hh @ W0 -> g_h1h
    gemm_fp16<NHID, 2><<<gg, 256, SMEM_GEMM>>>((float*)d_out, NN);  // g_h1h @ W1 -> out
}

// round 12
// speedup vs baseline: 1.0025x; 1.0025x over previous
#include <cuda_runtime.h>
#include <cuda_fp16.h>
#include <cstdint>

// Problem constants
#define NN   50000
#define EE   800000
#define NIN  128
#define NHID 256
#define XV4  (NN * NIN / 4)     // 1.6M float4 in x

// ---------------- scratch (no allocations allowed) ----------------
__device__ int    g_deg[NN];                  // edge-only degree
__device__ float  g_dinv[NN];
__device__ int    g_ptr[NN + 1];
__device__ int    g_cur[NN];
__device__ int    g_src[EE];
__device__ __half g_xs [(size_t)NN * NIN];    // dinv[j] * x[j], fp16 (agg input)
__device__ __half g_hh [(size_t)NN * NIN];    // aggregated features, fp16
__device__ __half g_h1h[(size_t)NN * NHID];   // hidden layer, fp16
__device__ __half g_w0t[NHID * NIN];          // W0^T [n][k] fp16
__device__ __half g_w1t[NHID * NHID];         // W1^T [n][k] fp16

// ---------------- zero degree array ----------------
__global__ void k_zero() {
    int i = blockIdx.x * blockDim.x + threadIdx.x;
    if (i < NN) g_deg[i] = 0;
}

// ---------------- per-thread edge dtype probe ----------------
// int32 data reinterpreted as int64 gives values >= 2^32 unless the hi word is
// zero (p ~ 2e-5 per probe for ids < 50000). Broadcast L1 hits across threads.
__device__ __forceinline__ int probe_is64(const void* __restrict__ ei) {
    const long long* p = (const long long*)ei;
    int ok = 1;
    #pragma unroll
    for (int t = 0; t < 4; t++) {
        long long v = __ldg(&p[t]);
        ok &= (v >= 0 && v < NN) ? 1 : 0;
    }
    return ok;
}

// ---------------- prep: W transpose to fp16 + edge degree count ----------------
__global__ void k_prep(const void* __restrict__ ei,
                       const float* __restrict__ W0, const float* __restrict__ W1) {
    int i = blockIdx.x * blockDim.x + threadIdx.x;
    if (i < NHID * NIN) {           // W0^T: i = n*128 + k
        int n = i >> 7, k = i & 127;
        g_w0t[i] = __float2half_rn(W0[k * NHID + n]);
    }
    if (i < NHID * NHID) {          // W1^T: i = n*256 + k
        int n = i >> 8, k = i & 255;
        g_w1t[i] = __float2half_rn(W1[k * NHID + n]);
    }
    if (i < EE / 4) {               // degree count, 4 edges/thread
        int e4 = 4 * i;
        int c0, c1, c2, c3;
        if (probe_is64(ei)) {
            const longlong2* p = (const longlong2*)((const long long*)ei + EE + e4);
            longlong2 a = p[0], b = p[1];
            c0 = (int)a.x; c1 = (int)a.y; c2 = (int)b.x; c3 = (int)b.y;
        } else {
            int4 v = *(const int4*)((const int*)ei + EE + e4);
            c0 = v.x; c1 = v.y; c2 = v.z; c3 = v.w;
        }
        atomicAdd(&g_deg[c0], 1);
        atomicAdd(&g_deg[c1], 1);
        atomicAdd(&g_deg[c2], 1);
        atomicAdd(&g_deg[c3], 1);
    }
}

// ---------------- single-block scan: deg -> ptr/cur, dinv ----------------
#define SCT 1024
#define SCH ((NN + SCT - 1) / SCT)   // 49 elements per thread
__global__ void __launch_bounds__(SCT) k_scan() {
    __shared__ int sh[SCT];
    int t = threadIdx.x;
    int start = t * SCH;
    int end   = min(start + SCH, NN);
    int sum = 0;
    for (int i = start; i < end; i++) {
        int d = g_deg[i];
        g_dinv[i] = rsqrtf((float)(d + 1));   // +1 self loop
        sum += d;
    }
    sh[t] = sum;
    __syncthreads();
    for (int off = 1; off < SCT; off <<= 1) {
        int v = (t >= off) ? sh[t - off] : 0;
        __syncthreads();
        sh[t] += v;
        __syncthreads();
    }
    int acc = sh[t] - sum;   // exclusive prefix of this thread's chunk
    for (int i = start; i < end; i++) {
        g_ptr[i] = acc;
        g_cur[i] = acc;
        acc += g_deg[i];
    }
    if (t == 0) g_ptr[NN] = EE;
}

// ---------------- fill CSR (4 edges / thread) + build xs = dinv*x (fp16) ----------------
__global__ void k_fillx(const float* __restrict__ x, const void* __restrict__ ei) {
    int i = blockIdx.x * blockDim.x + threadIdx.x;
    if (i < EE / 4) {
        int e4 = 4 * i;
        int r0, r1, r2, r3, c0, c1, c2, c3;
        if (probe_is64(ei)) {
            const longlong2* pr = (const longlong2*)((const long long*)ei + e4);
            const longlong2* pc = (const longlong2*)((const long long*)ei + EE + e4);
            longlong2 a = pr[0], b = pr[1], c = pc[0], d = pc[1];
            r0 = (int)a.x; r1 = (int)a.y; r2 = (int)b.x; r3 = (int)b.y;
            c0 = (int)c.x; c1 = (int)c.y; c2 = (int)d.x; c3 = (int)d.y;
        } else {
            int4 a = *(const int4*)((const int*)ei + e4);
            int4 b = *(const int4*)((const int*)ei + EE + e4);
            r0 = a.x; r1 = a.y; r2 = a.z; r3 = a.w;
            c0 = b.x; c1 = b.y; c2 = b.z; c3 = b.w;
        }
        g_src[atomicAdd(&g_cur[c0], 1)] = r0;
        g_src[atomicAdd(&g_cur[c1], 1)] = r1;
        g_src[atomicAdd(&g_cur[c2], 1)] = r2;
        g_src[atomicAdd(&g_cur[c3], 1)] = r3;
    }
    if (i < XV4) {                   // xs: one float4 (4 features) per thread
        int row = i >> 5;            // 32 float4 per row
        float dj = __ldg(&g_dinv[row]);   // broadcast across 32 threads
        float4 v = ((const float4*)x)[i];
        __half2 h0 = __floats2half2_rn(dj * v.x, dj * v.y);
        __half2 h1 = __floats2half2_rn(dj * v.z, dj * v.w);
        uint2 u;
        u.x = *(uint32_t*)&h0;
        u.y = *(uint32_t*)&h1;
        ((uint2*)g_xs)[i] = u;
    }
}

// ---------------- aggregation: warp per target node, prescaled fp16 gather ----------------
// h[i] = dinv[i] * ( xs[i] + sum_{(j,i)} xs[j] )
__global__ void __launch_bounds__(256) k_agg() {
    int w = (blockIdx.x * blockDim.x + threadIdx.x) >> 5;
    int lane = threadIdx.x & 31;
    if (w >= NN) return;
    float di = g_dinv[w];
    const uint2* __restrict__ xs = (const uint2*)g_xs;   // 32 uint2 per row

    uint2 raw = xs[(size_t)w * 32 + lane];               // self loop (already * dinv)
    float2 s0 = __half22float2(*(const __half2*)&raw.x);
    float2 s1 = __half22float2(*(const __half2*)&raw.y);
    float4 a;
    a.x = s0.x; a.y = s0.y; a.z = s1.x; a.w = s1.y;

    int s = g_ptr[w], e = g_ptr[w + 1];
    #pragma unroll 2
    for (int k = s; k < e; k++) {
        int  j  = __ldg(&g_src[k]);
        uint2 r = xs[(size_t)j * 32 + lane];
        float2 v0 = __half22float2(*(const __half2*)&r.x);
        float2 v1 = __half22float2(*(const __half2*)&r.y);
        a.x += v0.x;
        a.y += v0.y;
        a.z += v1.x;
        a.w += v1.y;
    }
    a.x *= di; a.y *= di; a.z *= di; a.w *= di;
    __half2 o0 = __floats2half2_rn(a.x, a.y);
    __half2 o1 = __floats2half2_rn(a.z, a.w);
    uint2 u;
    u.x = *(uint32_t*)&o0;
    u.y = *(uint32_t*)&o1;
    ((uint2*)g_hh)[(size_t)w * 32 + lane] = u;
}

// ---------------- FP16 tensor-core GEMM + ReLU (R7 synchronous version) ----------------
// Block tile 128x128, K-slab 64, 8 warps (2M x 4N), warp tile 64x32.
// mma.sync.aligned.m16n8k16.row.col.f32.f16.f16.f32
#define AST 36   // smem row stride in 32-bit words (32 data + 4 pad); bank=4*r4+c4

__device__ __forceinline__ void mma_fp16(float& d0, float& d1, float& d2, float& d3,
                                         uint32_t a0, uint32_t a1, uint32_t a2, uint32_t a3,
                                         uint32_t b0, uint32_t b1) {
    asm volatile(
        "mma.sync.aligned.m16n8k16.row.col.f32.f16.f16.f32 "
        "{%0,%1,%2,%3}, {%4,%5,%6,%7}, {%8,%9}, {%0,%1,%2,%3};"
        : "+f"(d0), "+f"(d1), "+f"(d2), "+f"(d3)
        : "r"(a0), "r"(a1), "r"(a2), "r"(a3), "r"(b0), "r"(b1));
}

// LAYER 1: A = g_hh (K=128), WT = g_w0t, C = g_h1h (fp16)
// LAYER 2: A = g_h1h (K=256), WT = g_w1t, C = Cout (fp32)
template<int K, int LAYER>
__global__ void __launch_bounds__(256) gemm_fp16(float* __restrict__ Cout, int M) {
    const __half* __restrict__ A  = (LAYER == 1) ? g_hh : g_h1h;
    const __half* __restrict__ WT = (LAYER == 1) ? g_w0t : g_w1t;

    __shared__ uint32_t As[128 * AST];   // [row][k-words]
    __shared__ uint32_t Bs[128 * AST];   // [n][k-words]

    int tid  = threadIdx.x;
    int lane = tid & 31;
    int wid  = tid >> 5;
    int wM = (wid >> 2) * 64;
    int wN = (wid & 3) * 32;
    int r4 = lane >> 2;
    int c4 = lane & 3;

    int brow = blockIdx.x * 128;
    int bcol = blockIdx.y * 128;

    float acc[4][4][4];
    #pragma unroll
    for (int mt = 0; mt < 4; mt++)
        #pragma unroll
        for (int nt = 0; nt < 4; nt++)
            #pragma unroll
            for (int r = 0; r < 4; r++) acc[mt][nt][r] = 0.f;

    for (int k0 = 0; k0 < K; k0 += 64) {
        // A tile: 128 rows x 64 halves = 2048 uint2; 8 per thread
        #pragma unroll
        for (int t = 0; t < 8; t++) {
            int idx = tid + t * 256;
            int row = idx >> 4;            // 16 uint2 per row-slab
            int c   = idx & 15;
            uint2 v = make_uint2(0u, 0u);
            int grow = brow + row;
            if (grow < M)
                v = ((const uint2*)(A + (size_t)grow * K))[(k0 >> 2) + c];
            *(uint2*)&As[row * AST + c * 2] = v;
        }
        // B tile: 128 n-rows x 64 halves from WT
        #pragma unroll
        for (int t = 0; t < 8; t++) {
            int idx = tid + t * 256;
            int row = idx >> 4;
            int c   = idx & 15;
            uint2 v = ((const uint2*)(WT + (size_t)(bcol + row) * K))[(k0 >> 2) + c];
            *(uint2*)&Bs[row * AST + c * 2] = v;
        }
        __syncthreads();

        #pragma unroll
        for (int s = 0; s < 4; s++) {      // 4 x k16 steps
            int kw = s * 8;
            uint32_t af[4][4];
            #pragma unroll
            for (int mt = 0; mt < 4; mt++) {
                int r = wM + mt * 16 + r4;
                af[mt][0] = As[r * AST + c4 + kw];
                af[mt][1] = As[(r + 8) * AST + c4 + kw];
                af[mt][2] = As[r * AST + c4 + 4 + kw];
                af[mt][3] = As[(r + 8) * AST + c4 + 4 + kw];
            }
            uint32_t bf[4][2];
            #pragma unroll
            for (int nt = 0; nt < 4; nt++) {
                int n = wN + nt * 8 + r4;
                bf[nt][0] = Bs[n * AST + c4 + kw];
                bf[nt][1] = Bs[n * AST + c4 + 4 + kw];
            }
            #pragma unroll
            for (int mt = 0; mt < 4; mt++)
                #pragma unroll
                for (int nt = 0; nt < 4; nt++)
                    mma_fp16(acc[mt][nt][0], acc[mt][nt][1], acc[mt][nt][2], acc[mt][nt][3],
                             af[mt][0], af[mt][1], af[mt][2], af[mt][3],
                             bf[nt][0], bf[nt][1]);
        }
        __syncthreads();
    }

    // epilogue
    #pragma unroll
    for (int mt = 0; mt < 4; mt++) {
        int row0 = brow + wM + mt * 16 + r4;
        #pragma unroll
        for (int nt = 0; nt < 4; nt++) {
            int col = bcol + wN + nt * 8 + c4 * 2;
            if (LAYER == 1) {
                if (row0 < M) {
                    __half2 h = __floats2half2_rn(fmaxf(acc[mt][nt][0], 0.f),
                                                  fmaxf(acc[mt][nt][1], 0.f));
                    *(__half2*)(g_h1h + (size_t)row0 * NHID + col) = h;
                }
                if (row0 + 8 < M) {
                    __half2 h = __floats2half2_rn(fmaxf(acc[mt][nt][2], 0.f),
                                                  fmaxf(acc[mt][nt][3], 0.f));
                    *(__half2*)(g_h1h + (size_t)(row0 + 8) * NHID + col) = h;
                }
            } else {
                if (row0 < M) {
                    float2 v;
                    v.x = fmaxf(acc[mt][nt][0], 0.f);
                    v.y = fmaxf(acc[mt][nt][1], 0.f);
                    *(float2*)(Cout + (size_t)row0 * NHID + col) = v;
                }
                if (row0 + 8 < M) {
                    float2 v;
                    v.x = fmaxf(acc[mt][nt][2], 0.f);
                    v.y = fmaxf(acc[mt][nt][3], 0.f);
                    *(float2*)(Cout + (size_t)(row0 + 8) * NHID + col) = v;
                }
            }
        }
    }
}

extern "C" void kernel_launch(void* const* d_in, const int* in_sizes, int n_in,
                              void* d_out, int out_size) {
    const float* x  = nullptr;
    const float* W0 = nullptr;
    const float* W1 = nullptr;
    const void*  ei = nullptr;
    for (int i = 0; i < n_in; i++) {
        long long sz = in_sizes[i];
        if      (sz == (long long)NN * NIN)    x  = (const float*)d_in[i];
        else if (sz == (long long)NIN * NHID)  W0 = (const float*)d_in[i];
        else if (sz == (long long)NHID * NHID) W1 = (const float*)d_in[i];
        else if (sz == (long long)2 * EE)      ei = d_in[i];
    }

    k_zero <<<(NN + 255) / 256, 256>>>();
    k_prep <<<(EE / 4 + 255) / 256, 256>>>(ei, W0, W1);
    k_scan <<<1, SCT>>>();
    k_fillx<<<(XV4 + 255) / 256, 256>>>(x, ei);
    k_agg  <<<(NN * 32 + 255) / 256, 256>>>();

    dim3 gg((NN + 127) / 128, NHID / 128);
    gemm_fp16<NIN,  1><<<gg, 256>>>(nullptr, NN);          // g_hh @ W0 -> g_h1h
    gemm_fp16<NHID, 2><<<gg, 256>>>((float*)d_out, NN);    // g_h1h @ W1 -> out
}

// round 14
// speedup vs baseline: 1.7952x; 1.7908x over previous
#include <cuda_runtime.h>
#include <cuda_fp16.h>
#include <cstdint>

// Problem constants
#define NN   50000
#define EE   800000
#define NIN  128
#define NHID 256

#define SCAN_B  1024
#define SCAN_NB ((NN + SCAN_B - 1) / SCAN_B)   // 49
#define XV4     (NN * NIN / 4)                 // 1.6M float4 in x

// ---------------- scratch (no allocations allowed) ----------------
__device__ int    g_is64;
__device__ int    g_deg[NN];
__device__ float  g_dinv[NN];
__device__ int    g_ptr[NN + 1];
__device__ int    g_cur[NN];
__device__ int    g_src[EE];
__device__ int    g_bsum[SCAN_NB];
__device__ __half g_xh [(size_t)NN * NIN];    // x in fp16 (agg input)
__device__ __half g_hh [(size_t)NN * NIN];    // aggregated features, fp16
__device__ __half g_h1h[(size_t)NN * NHID];   // hidden layer, fp16
__device__ __half g_w0t[NHID * NIN];          // W0^T [n][k] fp16
__device__ __half g_w1t[NHID * NHID];         // W1^T [n][k] fp16

// ---------------- prep: deg init + dtype detect + x->fp16 + W transpose ----------------
__global__ void k_prep(const float* __restrict__ x, const void* __restrict__ ei,
                       const float* __restrict__ W0, const float* __restrict__ W1) {
    int i = blockIdx.x * blockDim.x + threadIdx.x;
    if (i < NN) g_deg[i] = 1;   // self loop
    if (i == 0) {
        const long long* p = (const long long*)ei;
        int ok = 1;
        #pragma unroll
        for (int t = 0; t < 16; t++) {
            long long v = p[t];
            ok &= (v >= 0 && v < NN) ? 1 : 0;
        }
        g_is64 = ok;
    }
    if (i < XV4) {
        float4 v = ((const float4*)x)[i];
        __half2 h0 = __floats2half2_rn(v.x, v.y);
        __half2 h1 = __floats2half2_rn(v.z, v.w);
        uint2 u;
        u.x = *(uint32_t*)&h0;
        u.y = *(uint32_t*)&h1;
        ((uint2*)g_xh)[i] = u;
    }
    if (i < NHID * NIN) {           // W0^T: i = n*128 + k
        int n = i >> 7, k = i & 127;
        g_w0t[i] = __float2half_rn(W0[k * NHID + n]);
    }
    if (i < NHID * NHID) {          // W1^T: i = n*256 + k
        int n = i >> 8, k = i & 255;
        g_w1t[i] = __float2half_rn(W1[k * NHID + n]);
    }
}

// ---------------- degree count (4 edges / thread) ----------------
__global__ void k_count(const void* __restrict__ ei) {
    int e4 = 4 * (blockIdx.x * blockDim.x + threadIdx.x);
    if (e4 >= EE) return;
    int c0, c1, c2, c3;
    if (g_is64) {
        const longlong2* p = (const longlong2*)((const long long*)ei + EE + e4);
        longlong2 a = p[0], b = p[1];
        c0 = (int)a.x; c1 = (int)a.y; c2 = (int)b.x; c3 = (int)b.y;
    } else {
        int4 v = *(const int4*)((const int*)ei + EE + e4);
        c0 = v.x; c1 = v.y; c2 = v.z; c3 = v.w;
    }
    atomicAdd(&g_deg[c0], 1);
    atomicAdd(&g_deg[c1], 1);
    atomicAdd(&g_deg[c2], 1);
    atomicAdd(&g_deg[c3], 1);
}

// ---------------- scan1: block-scan of (deg-1), also computes dinv ----------------
__global__ void k_scan1() {
    __shared__ int sh[SCAN_B];
    int gid = blockIdx.x * SCAN_B + threadIdx.x;
    int d = (gid < NN) ? g_deg[gid] : 1;
    int v = d - 1;
    if (gid < NN) g_dinv[gid] = rsqrtf((float)d);
    sh[threadIdx.x] = v;
    __syncthreads();
    for (int off = 1; off < SCAN_B; off <<= 1) {
        int t = (threadIdx.x >= off) ? sh[threadIdx.x - off] : 0;
        __syncthreads();
        sh[threadIdx.x] += t;
        __syncthreads();
    }
    if (gid < NN) g_ptr[gid] = sh[threadIdx.x] - v;   // exclusive within block
    if (threadIdx.x == SCAN_B - 1) g_bsum[blockIdx.x] = sh[SCAN_B - 1];
}

// scan3: each block sums its predecessor block-sums inline
__global__ void k_scan3() {
    __shared__ int sh[64];
    __shared__ int s_off;
    int t = threadIdx.x;
    if (t < 64) sh[t] = (t < SCAN_NB && t < blockIdx.x) ? g_bsum[t] : 0;
    __syncthreads();
    if (t == 0) {
        int acc = 0;
        #pragma unroll
        for (int b = 0; b < 64; b++) acc += sh[b];
        s_off = acc;
    }
    __syncthreads();
    int gid = blockIdx.x * SCAN_B + t;
    if (gid < NN) {
        int p = g_ptr[gid] + s_off;
        g_ptr[gid] = p;
        g_cur[gid] = p;
    }
    if (gid == 0) g_ptr[NN] = EE;
}

// ---------------- fill CSR (4 edges / thread) ----------------
__global__ void k_fill(const void* __restrict__ ei) {
    int e4 = 4 * (blockIdx.x * blockDim.x + threadIdx.x);
    if (e4 >= EE) return;
    int r0, r1, r2, r3, c0, c1, c2, c3;
    if (g_is64) {
        const longlong2* pr = (const longlong2*)((const long long*)ei + e4);
        const longlong2* pc = (const longlong2*)((const long long*)ei + EE + e4);
        longlong2 a = pr[0], b = pr[1], c = pc[0], d = pc[1];
        r0 = (int)a.x; r1 = (int)a.y; r2 = (int)b.x; r3 = (int)b.y;
        c0 = (int)c.x; c1 = (int)c.y; c2 = (int)d.x; c3 = (int)d.y;
    } else {
        int4 a = *(const int4*)((const int*)ei + e4);
        int4 b = *(const int4*)((const int*)ei + EE + e4);
        r0 = a.x; r1 = a.y; r2 = a.z; r3 = a.w;
        c0 = b.x; c1 = b.y; c2 = b.z; c3 = b.w;
    }
    g_src[atomicAdd(&g_cur[c0], 1)] = r0;
    g_src[atomicAdd(&g_cur[c1], 1)] = r1;
    g_src[atomicAdd(&g_cur[c2], 1)] = r2;
    g_src[atomicAdd(&g_cur[c3], 1)] = r3;
}

// ---------------- aggregation: warp per target node, fp16 in/out ----------------
__global__ void __launch_bounds__(256) k_agg() {
    int w = (blockIdx.x * blockDim.x + threadIdx.x) >> 5;
    int lane = threadIdx.x & 31;
    if (w >= NN) return;
    float di = g_dinv[w];
    const uint2* __restrict__ xh = (const uint2*)g_xh;   // 32 uint2 per row

    uint2 raw = xh[(size_t)w * 32 + lane];               // self loop
    float2 s0 = __half22float2(*(const __half2*)&raw.x);
    float2 s1 = __half22float2(*(const __half2*)&raw.y);
    float4 a;
    a.x = di * s0.x; a.y = di * s0.y; a.z = di * s1.x; a.w = di * s1.y;

    int s = g_ptr[w], e = g_ptr[w + 1];
    #pragma unroll 2
    for (int k = s; k < e; k++) {
        int   j  = __ldg(&g_src[k]);
        float wj = __ldg(&g_dinv[j]);
        uint2 r  = xh[(size_t)j * 32 + lane];
        float2 v0 = __half22float2(*(const __half2*)&r.x);
        float2 v1 = __half22float2(*(const __half2*)&r.y);
        a.x = fmaf(wj, v0.x, a.x);
        a.y = fmaf(wj, v0.y, a.y);
        a.z = fmaf(wj, v1.x, a.z);
        a.w = fmaf(wj, v1.y, a.w);
    }
    a.x *= di; a.y *= di; a.z *= di; a.w *= di;
    __half2 o0 = __floats2half2_rn(a.x, a.y);
    __half2 o1 = __floats2half2_rn(a.z, a.w);
    uint2 u;
    u.x = *(uint32_t*)&o0;
    u.y = *(uint32_t*)&o1;
    ((uint2*)g_hh)[(size_t)w * 32 + lane] = u;
}

// ---------------- FP16 tensor-core GEMM + ReLU ----------------
// Block tile 128x128, K-slab 64, 8 warps (2M x 4N), warp tile 64x32.
// mma.sync.aligned.m16n8k16.row.col.f32.f16.f16.f32
#define AST 36   // smem row stride in 32-bit words (32 data + 4 pad); bank=4*r4+c4

__device__ __forceinline__ void mma_fp16(float& d0, float& d1, float& d2, float& d3,
                                         uint32_t a0, uint32_t a1, uint32_t a2, uint32_t a3,
                                         uint32_t b0, uint32_t b1) {
    asm volatile(
        "mma.sync.aligned.m16n8k16.row.col.f32.f16.f16.f32 "
        "{%0,%1,%2,%3}, {%4,%5,%6,%7}, {%8,%9}, {%0,%1,%2,%3};"
        : "+f"(d0), "+f"(d1), "+f"(d2), "+f"(d3)
        : "r"(a0), "r"(a1), "r"(a2), "r"(a3), "r"(b0), "r"(b1));
}

// LAYER 1: A = g_hh (K=128), WT = g_w0t, C = g_h1h (fp16)
// LAYER 2: A = g_h1h (K=256), WT = g_w1t, C = Cout (fp32)
template<int K, int LAYER>
__global__ void __launch_bounds__(256) gemm_fp16(float* __restrict__ Cout, int M) {
    const __half* __restrict__ A  = (LAYER == 1) ? g_hh : g_h1h;
    const __half* __restrict__ WT = (LAYER == 1) ? g_w0t : g_w1t;

    __shared__ uint32_t As[128 * AST];   // [row][k-words]
    __shared__ uint32_t Bs[128 * AST];   // [n][k-words]

    int tid  = threadIdx.x;
    int lane = tid & 31;
    int wid  = tid >> 5;
    int wM = (wid >> 2) * 64;
    int wN = (wid & 3) * 32;
    int r4 = lane >> 2;
    int c4 = lane & 3;

    int brow = blockIdx.x * 128;
    int bcol = blockIdx.y * 128;

    float acc[4][4][4];
    #pragma unroll
    for (int mt = 0; mt < 4; mt++)
        #pragma unroll
        for (int nt = 0; nt < 4; nt++)
            #pragma unroll
            for (int r = 0; r < 4; r++) acc[mt][nt][r] = 0.f;

    for (int k0 = 0; k0 < K; k0 += 64) {
        // A tile: 128 rows x 64 halves = 2048 uint2; 8 per thread
        #pragma unroll
        for (int t = 0; t < 8; t++) {
            int idx = tid + t * 256;
            int row = idx >> 4;            // 16 uint2 per row-slab
            int c   = idx & 15;
            uint2 v = make_uint2(0u, 0u);
            int grow = brow + row;
            if (grow < M)
                v = ((const uint2*)(A + (size_t)grow * K))[(k0 >> 2) + c];
            *(uint2*)&As[row * AST + c * 2] = v;
        }
        // B tile: 128 n-rows x 64 halves from WT
        #pragma unroll
        for (int t = 0; t < 8; t++) {
            int idx = tid + t * 256;
            int row = idx >> 4;
            int c   = idx & 15;
            uint2 v = ((const uint2*)(WT + (size_t)(bcol + row) * K))[(k0 >> 2) + c];
            *(uint2*)&Bs[row * AST + c * 2] = v;
        }
        __syncthreads();

        #pragma unroll
        for (int s = 0; s < 4; s++) {      // 4 x k16 steps
            int kw = s * 8;
            uint32_t af[4][4];
            #pragma unroll
            for (int mt = 0; mt < 4; mt++) {
                int r = wM + mt * 16 + r4;
                af[mt][0] = As[r * AST + c4 + kw];
                af[mt][1] = As[(r + 8) * AST + c4 + kw];
                af[mt][2] = As[r * AST + c4 + 4 + kw];
                af[mt][3] = As[(r + 8) * AST + c4 + 4 + kw];
            }
            uint32_t bf[4][2];
            #pragma unroll
            for (int nt = 0; nt < 4; nt++) {
                int n = wN + nt * 8 + r4;
                bf[nt][0] = Bs[n * AST + c4 + kw];
                bf[nt][1] = Bs[n * AST + c4 + 4 + kw];
            }
            #pragma unroll
            for (int mt = 0; mt < 4; mt++)
                #pragma unroll
                for (int nt = 0; nt < 4; nt++)
                    mma_fp16(acc[mt][nt][0], acc[mt][nt][1], acc[mt][nt][2], acc[mt][nt][3],
                             af[mt][0], af[mt][1], af[mt][2], af[mt][3],
                             bf[nt][0], bf[nt][1]);
        }
        __syncthreads();
    }

    // epilogue
    #pragma unroll
    for (int mt = 0; mt < 4; mt++) {
        int row0 = brow + wM + mt * 16 + r4;
        #pragma unroll
        for (int nt = 0; nt < 4; nt++) {
            int col = bcol + wN + nt * 8 + c4 * 2;
            if (LAYER == 1) {
                if (row0 < M) {
                    __half2 h = __floats2half2_rn(fmaxf(acc[mt][nt][0], 0.f),
                                                  fmaxf(acc[mt][nt][1], 0.f));
                    *(__half2*)(g_h1h + (size_t)row0 * NHID + col) = h;
                }
                if (row0 + 8 < M) {
                    __half2 h = __floats2half2_rn(fmaxf(acc[mt][nt][2], 0.f),
                                                  fmaxf(acc[mt][nt][3], 0.f));
                    *(__half2*)(g_h1h + (size_t)(row0 + 8) * NHID + col) = h;
                }
            } else {
                if (row0 < M) {
                    float2 v;
                    v.x = fmaxf(acc[mt][nt][0], 0.f);
                    v.y = fmaxf(acc[mt][nt][1], 0.f);
                    *(float2*)(Cout + (size_t)row0 * NHID + col) = v;
                }
                if (row0 + 8 < M) {
                    float2 v;
                    v.x = fmaxf(acc[mt][nt][2], 0.f);
                    v.y = fmaxf(acc[mt][nt][3], 0.f);
                    *(float2*)(Cout + (size_t)(row0 + 8) * NHID + col) = v;
                }
            }
        }
    }
}

extern "C" void kernel_launch(void* const* d_in, const int* in_sizes, int n_in,
                              void* d_out, int out_size) {
    const float* x  = nullptr;
    const float* W0 = nullptr;
    const float* W1 = nullptr;
    const void*  ei = nullptr;
    for (int i = 0; i < n_in; i++) {
        long long sz = in_sizes[i];
        if      (sz == (long long)NN * NIN)    x  = (const float*)d_in[i];
        else if (sz == (long long)NIN * NHID)  W0 = (const float*)d_in[i];
        else if (sz == (long long)NHID * NHID) W1 = (const float*)d_in[i];
        else if (sz == (long long)2 * EE)      ei = d_in[i];
    }

    k_prep <<<(XV4 + 255) / 256, 256>>>(x, ei, W0, W1);
    k_count<<<(EE / 4 + 255) / 256, 256>>>(ei);
    k_scan1<<<SCAN_NB, SCAN_B>>>();
    k_scan3<<<SCAN_NB, SCAN_B>>>();
    k_fill <<<(EE / 4 + 255) / 256, 256>>>(ei);

    k_agg<<<(NN * 32 + 255) / 256, 256>>>();

    dim3 gg((NN + 127) / 128, NHID / 128);
    gemm_fp16<NIN,  1><<<gg, 256>>>(nullptr, NN);          // g_hh @ W0 -> g_h1h
    gemm_fp16<NHID, 2><<<gg, 256>>>((float*)d_out, NN);    // g_h1h @ W1 -> out
}

// round 15
// speedup vs baseline: 1.8228x; 1.0154x over previous
#include <cuda_runtime.h>
#include <cuda_fp16.h>
#include <cstdint>

// Problem constants
#define NN   50000
#define EE   800000
#define NIN  128
#define NHID 256

#define SCAN_B  1024
#define SCAN_NB ((NN + SCAN_B - 1) / SCAN_B)   // 49
#define XV4     (NN * NIN / 4)                 // 1.6M float4 in x

// ---------------- scratch (no allocations allowed) ----------------
__device__ int    g_is64;
__device__ int    g_deg[NN];
__device__ float  g_dinv[NN];
__device__ int    g_ptr[NN + 1];
__device__ int    g_cur[NN];
__device__ int    g_src[EE];
__device__ int    g_bsum[SCAN_NB];
__device__ __half g_xh [(size_t)NN * NIN];    // x in fp16 (agg input)
__device__ __half g_hh [(size_t)NN * NIN];    // aggregated features, fp16
__device__ __half g_h1h[(size_t)NN * NHID];   // hidden layer, fp16
__device__ __half g_w0t[NHID * NIN];          // W0^T [n][k] fp16
__device__ __half g_w1t[NHID * NHID];         // W1^T [n][k] fp16

// ---------------- prep: deg init + dtype detect + x->fp16 + W transpose ----------------
__global__ void k_prep(const float* __restrict__ x, const void* __restrict__ ei,
                       const float* __restrict__ W0, const float* __restrict__ W1) {
    int i = blockIdx.x * blockDim.x + threadIdx.x;
    if (i < NN) g_deg[i] = 1;   // self loop
    if (i == 0) {
        const long long* p = (const long long*)ei;
        int ok = 1;
        #pragma unroll
        for (int t = 0; t < 16; t++) {
            long long v = p[t];
            ok &= (v >= 0 && v < NN) ? 1 : 0;
        }
        g_is64 = ok;
    }
    if (i < XV4) {
        float4 v = ((const float4*)x)[i];
        __half2 h0 = __floats2half2_rn(v.x, v.y);
        __half2 h1 = __floats2half2_rn(v.z, v.w);
        uint2 u;
        u.x = *(uint32_t*)&h0;
        u.y = *(uint32_t*)&h1;
        ((uint2*)g_xh)[i] = u;
    }
    if (i < NHID * NIN) {           // W0^T: i = n*128 + k
        int n = i >> 7, k = i & 127;
        g_w0t[i] = __float2half_rn(W0[k * NHID + n]);
    }
    if (i < NHID * NHID) {          // W1^T: i = n*256 + k
        int n = i >> 8, k = i & 255;
        g_w1t[i] = __float2half_rn(W1[k * NHID + n]);
    }
}

// ---------------- degree count (4 edges / thread) ----------------
__global__ void k_count(const void* __restrict__ ei) {
    int e4 = 4 * (blockIdx.x * blockDim.x + threadIdx.x);
    if (e4 >= EE) return;
    int c0, c1, c2, c3;
    if (g_is64) {
        const longlong2* p = (const longlong2*)((const long long*)ei + EE + e4);
        longlong2 a = p[0], b = p[1];
        c0 = (int)a.x; c1 = (int)a.y; c2 = (int)b.x; c3 = (int)b.y;
    } else {
        int4 v = *(const int4*)((const int*)ei + EE + e4);
        c0 = v.x; c1 = v.y; c2 = v.z; c3 = v.w;
    }
    atomicAdd(&g_deg[c0], 1);
    atomicAdd(&g_deg[c1], 1);
    atomicAdd(&g_deg[c2], 1);
    atomicAdd(&g_deg[c3], 1);
}

// ---------------- scan1: block-scan of (deg-1), also computes dinv ----------------
__global__ void k_scan1() {
    __shared__ int sh[SCAN_B];
    int gid = blockIdx.x * SCAN_B + threadIdx.x;
    int d = (gid < NN) ? g_deg[gid] : 1;
    int v = d - 1;
    if (gid < NN) g_dinv[gid] = rsqrtf((float)d);
    sh[threadIdx.x] = v;
    __syncthreads();
    for (int off = 1; off < SCAN_B; off <<= 1) {
        int t = (threadIdx.x >= off) ? sh[threadIdx.x - off] : 0;
        __syncthreads();
        sh[threadIdx.x] += t;
        __syncthreads();
    }
    if (gid < NN) g_ptr[gid] = sh[threadIdx.x] - v;   // exclusive within block
    if (threadIdx.x == SCAN_B - 1) g_bsum[blockIdx.x] = sh[SCAN_B - 1];
}

// scan3: each block sums its predecessor block-sums inline
__global__ void k_scan3() {
    __shared__ int sh[64];
    __shared__ int s_off;
    int t = threadIdx.x;
    if (t < 64) sh[t] = (t < SCAN_NB && t < blockIdx.x) ? g_bsum[t] : 0;
    __syncthreads();
    if (t == 0) {
        int acc = 0;
        #pragma unroll
        for (int b = 0; b < 64; b++) acc += sh[b];
        s_off = acc;
    }
    __syncthreads();
    int gid = blockIdx.x * SCAN_B + t;
    if (gid < NN) {
        int p = g_ptr[gid] + s_off;
        g_ptr[gid] = p;
        g_cur[gid] = p;
    }
    if (gid == 0) g_ptr[NN] = EE;
}

// ---------------- fill CSR (4 edges / thread) ----------------
__global__ void k_fill(const void* __restrict__ ei) {
    int e4 = 4 * (blockIdx.x * blockDim.x + threadIdx.x);
    if (e4 >= EE) return;
    int r0, r1, r2, r3, c0, c1, c2, c3;
    if (g_is64) {
        const longlong2* pr = (const longlong2*)((const long long*)ei + e4);
        const longlong2* pc = (const longlong2*)((const long long*)ei + EE + e4);
        longlong2 a = pr[0], b = pr[1], c = pc[0], d = pc[1];
        r0 = (int)a.x; r1 = (int)a.y; r2 = (int)b.x; r3 = (int)b.y;
        c0 = (int)c.x; c1 = (int)c.y; c2 = (int)d.x; c3 = (int)d.y;
    } else {
        int4 a = *(const int4*)((const int*)ei + e4);
        int4 b = *(const int4*)((const int*)ei + EE + e4);
        r0 = a.x; r1 = a.y; r2 = a.z; r3 = a.w;
        c0 = b.x; c1 = b.y; c2 = b.z; c3 = b.w;
    }
    g_src[atomicAdd(&g_cur[c0], 1)] = r0;
    g_src[atomicAdd(&g_cur[c1], 1)] = r1;
    g_src[atomicAdd(&g_cur[c2], 1)] = r2;
    g_src[atomicAdd(&g_cur[c3], 1)] = r3;
}

// ---------------- aggregation: warp per target node, fp16 in/out ----------------
__global__ void __launch_bounds__(256) k_agg() {
    int w = (blockIdx.x * blockDim.x + threadIdx.x) >> 5;
    int lane = threadIdx.x & 31;
    if (w >= NN) return;
    float di = g_dinv[w];
    const uint2* __restrict__ xh = (const uint2*)g_xh;   // 32 uint2 per row

    uint2 raw = xh[(size_t)w * 32 + lane];               // self loop
    float2 s0 = __half22float2(*(const __half2*)&raw.x);
    float2 s1 = __half22float2(*(const __half2*)&raw.y);
    float4 a;
    a.x = di * s0.x; a.y = di * s0.y; a.z = di * s1.x; a.w = di * s1.y;

    int s = g_ptr[w], e = g_ptr[w + 1];
    #pragma unroll 2
    for (int k = s; k < e; k++) {
        int   j  = __ldg(&g_src[k]);
        float wj = __ldg(&g_dinv[j]);
        uint2 r  = xh[(size_t)j * 32 + lane];
        float2 v0 = __half22float2(*(const __half2*)&r.x);
        float2 v1 = __half22float2(*(const __half2*)&r.y);
        a.x = fmaf(wj, v0.x, a.x);
        a.y = fmaf(wj, v0.y, a.y);
        a.z = fmaf(wj, v1.x, a.z);
        a.w = fmaf(wj, v1.y, a.w);
    }
    a.x *= di; a.y *= di; a.z *= di; a.w *= di;
    __half2 o0 = __floats2half2_rn(a.x, a.y);
    __half2 o1 = __floats2half2_rn(a.z, a.w);
    uint2 u;
    u.x = *(uint32_t*)&o0;
    u.y = *(uint32_t*)&o1;
    ((uint2*)g_hh)[(size_t)w * 32 + lane] = u;
}

// ---------------- FP16 tensor-core GEMM + ReLU, cp.async double-buffered ----------------
// Block tile 128x128, K-slab 64, 8 warps (2M x 4N), warp tile 64x32.
#define AST 36                      // smem row stride in words; 144B, 16B-aligned
#define SLAB_W (128 * AST)          // words per slab buffer
#define SMEM_GEMM (4 * SLAB_W * 4)  // A0,A1,B0,B1 in bytes (73728)

__device__ __forceinline__ void cp16(uint32_t dst_smem, const void* src, int sz) {
    asm volatile("cp.async.cg.shared.global [%0], [%1], 16, %2;\n"
                 :: "r"(dst_smem), "l"(src), "r"(sz));
}
__device__ __forceinline__ void cp_commit() {
    asm volatile("cp.async.commit_group;\n");
}
template<int N>
__device__ __forceinline__ void cp_wait() {
    asm volatile("cp.async.wait_group %0;\n" :: "n"(N));
}

__device__ __forceinline__ void mma_fp16(float& d0, float& d1, float& d2, float& d3,
                                         uint32_t a0, uint32_t a1, uint32_t a2, uint32_t a3,
                                         uint32_t b0, uint32_t b1) {
    asm volatile(
        "mma.sync.aligned.m16n8k16.row.col.f32.f16.f16.f32 "
        "{%0,%1,%2,%3}, {%4,%5,%6,%7}, {%8,%9}, {%0,%1,%2,%3};"
        : "+f"(d0), "+f"(d1), "+f"(d2), "+f"(d3)
        : "r"(a0), "r"(a1), "r"(a2), "r"(a3), "r"(b0), "r"(b1));
}

// LAYER 1: A = g_hh (K=128), WT = g_w0t, C = g_h1h (fp16)
// LAYER 2: A = g_h1h (K=256), WT = g_w1t, C = Cout (fp32)
template<int K, int LAYER>
__global__ void __launch_bounds__(256) gemm_fp16(float* __restrict__ Cout, int M) {
    const __half* __restrict__ A  = (LAYER == 1) ? g_hh : g_h1h;
    const __half* __restrict__ WT = (LAYER == 1) ? g_w0t : g_w1t;

    extern __shared__ uint32_t smem[];
    uint32_t* Abuf[2] = { smem,             smem + SLAB_W };
    uint32_t* Bbuf[2] = { smem + 2*SLAB_W,  smem + 3*SLAB_W };

    int tid  = threadIdx.x;
    int lane = tid & 31;
    int wid  = tid >> 5;
    int wM = (wid >> 2) * 64;
    int wN = (wid & 3) * 32;
    int r4 = lane >> 2;
    int c4 = lane & 3;

    int brow = blockIdx.x * 128;
    int bcol = blockIdx.y * 128;

    // async load of one 64-k slab into buffer b (A: rows may be OOB -> zfill)
    auto load_slab = [&](int b, int k0) {
        uint32_t a_base = (uint32_t)__cvta_generic_to_shared(Abuf[b]);
        uint32_t b_base = (uint32_t)__cvta_generic_to_shared(Bbuf[b]);
        #pragma unroll
        for (int t = 0; t < 4; t++) {
            int idx = tid + t * 256;        // uint4 index, 8 per row
            int row = idx >> 3;
            int c   = idx & 7;
            int grow = brow + row;
            int ok = (grow < M);
            const __half* srcA = A + (size_t)(ok ? grow : 0) * K + k0 + c * 8;
            cp16(a_base + (row * AST + c * 4) * 4, srcA, ok ? 16 : 0);
            const __half* srcB = WT + (size_t)(bcol + row) * K + k0 + c * 8;
            cp16(b_base + (row * AST + c * 4) * 4, srcB, 16);
        }
        cp_commit();
    };

    float acc[4][4][4];
    #pragma unroll
    for (int mt = 0; mt < 4; mt++)
        #pragma unroll
        for (int nt = 0; nt < 4; nt++)
            #pragma unroll
            for (int r = 0; r < 4; r++) acc[mt][nt][r] = 0.f;

    const int NSLAB = K / 64;
    load_slab(0, 0);

    #pragma unroll
    for (int i = 0; i < NSLAB; i++) {
        if (i + 1 < NSLAB) {
            load_slab((i + 1) & 1, (i + 1) * 64);
            cp_wait<1>();
        } else {
            cp_wait<0>();
        }
        __syncthreads();

        const uint32_t* As = Abuf[i & 1];
        const uint32_t* Bs = Bbuf[i & 1];
        #pragma unroll
        for (int s = 0; s < 4; s++) {      // 4 x k16 steps
            int kw = s * 8;
            uint32_t af[4][4];
            #pragma unroll
            for (int mt = 0; mt < 4; mt++) {
                int r = wM + mt * 16 + r4;
                af[mt][0] = As[r * AST + c4 + kw];
                af[mt][1] = As[(r + 8) * AST + c4 + kw];
                af[mt][2] = As[r * AST + c4 + 4 + kw];
                af[mt][3] = As[(r + 8) * AST + c4 + 4 + kw];
            }
            uint32_t bf[4][2];
            #pragma unroll
            for (int nt = 0; nt < 4; nt++) {
                int n = wN + nt * 8 + r4;
                bf[nt][0] = Bs[n * AST + c4 + kw];
                bf[nt][1] = Bs[n * AST + c4 + 4 + kw];
            }
            #pragma unroll
            for (int mt = 0; mt < 4; mt++)
                #pragma unroll
                for (int nt = 0; nt < 4; nt++)
                    mma_fp16(acc[mt][nt][0], acc[mt][nt][1], acc[mt][nt][2], acc[mt][nt][3],
                             af[mt][0], af[mt][1], af[mt][2], af[mt][3],
                             bf[nt][0], bf[nt][1]);
        }
        __syncthreads();   // all reads of this buffer done before it is re-filled
    }

    // epilogue
    #pragma unroll
    for (int mt = 0; mt < 4; mt++) {
        int row0 = brow + wM + mt * 16 + r4;
        #pragma unroll
        for (int nt = 0; nt < 4; nt++) {
            int col = bcol + wN + nt * 8 + c4 * 2;
            if (LAYER == 1) {
                if (row0 < M) {
                    __half2 h = __floats2half2_rn(fmaxf(acc[mt][nt][0], 0.f),
                                                  fmaxf(acc[mt][nt][1], 0.f));
                    *(__half2*)(g_h1h + (size_t)row0 * NHID + col) = h;
                }
                if (row0 + 8 < M) {
                    __half2 h = __floats2half2_rn(fmaxf(acc[mt][nt][2], 0.f),
                                                  fmaxf(acc[mt][nt][3], 0.f));
                    *(__half2*)(g_h1h + (size_t)(row0 + 8) * NHID + col) = h;
                }
            } else {
                if (row0 < M) {
                    float2 v;
                    v.x = fmaxf(acc[mt][nt][0], 0.f);
                    v.y = fmaxf(acc[mt][nt][1], 0.f);
                    *(float2*)(Cout + (size_t)row0 * NHID + col) = v;
                }
                if (row0 + 8 < M) {
                    float2 v;
                    v.x = fmaxf(acc[mt][nt][2], 0.f);
                    v.y = fmaxf(acc[mt][nt][3], 0.f);
                    *(float2*)(Cout + (size_t)(row0 + 8) * NHID + col) = v;
                }
            }
        }
    }
}

extern "C" void kernel_launch(void* const* d_in, const int* in_sizes, int n_in,
                              void* d_out, int out_size) {
    const float* x  = nullptr;
    const float* W0 = nullptr;
    const float* W1 = nullptr;
    const void*  ei = nullptr;
    for (int i = 0; i < n_in; i++) {
        long long sz = in_sizes[i];
        if      (sz == (long long)NN * NIN)    x  = (const float*)d_in[i];
        else if (sz == (long long)NIN * NHID)  W0 = (const float*)d_in[i];
        else if (sz == (long long)NHID * NHID) W1 = (const float*)d_in[i];
        else if (sz == (long long)2 * EE)      ei = d_in[i];
    }

    cudaFuncSetAttribute(gemm_fp16<NIN, 1>,
                         cudaFuncAttributeMaxDynamicSharedMemorySize, SMEM_GEMM);
    cudaFuncSetAttribute(gemm_fp16<NHID, 2>,
                         cudaFuncAttributeMaxDynamicSharedMemorySize, SMEM_GEMM);

    k_prep <<<(XV4 + 255) / 256, 256>>>(x, ei, W0, W1);
    k_count<<<(EE / 4 + 255) / 256, 256>>>(ei);
    k_scan1<<<SCAN_NB, SCAN_B>>>();
    k_scan3<<<SCAN_NB, SCAN_B>>>();
    k_fill <<<(EE / 4 + 255) / 256, 256>>>(ei);

    k_agg<<<(NN * 32 + 255) / 256, 256>>>();

    dim3 gg((NN + 127) / 128, NHID / 128);
    gemm_fp16<NIN,  1><<<gg, 256, SMEM_GEMM>>>(nullptr, NN);        // g_hh @ W0 -> g_h1h
    gemm_fp16<NHID, 2><<<gg, 256, SMEM_GEMM>>>((float*)d_out, NN);  // g_h1h @ W1 -> out
}

// round 17
// speedup vs baseline: 1.9485x; 1.0690x over previous
#include <cuda_runtime.h>
#include <cuda_fp16.h>
#include <cstdint>

// Problem constants
#define NN   50000
#define EE   800000
#define NIN  128
#define NHID 256

#define SCAN_B  1024
#define SCAN_NB ((NN + SCAN_B - 1) / SCAN_B)   // 49
#define XV4     (NN * NIN / 4)                 // 1.6M float4 in x

// ---------------- scratch (no allocations allowed) ----------------
__device__ int    g_is64;
__device__ int    g_deg[NN];
__device__ float  g_dinv[NN];
__device__ int    g_ptr[NN + 1];
__device__ int    g_cur[NN];
__device__ int    g_src[EE];
__device__ int    g_bsum[SCAN_NB];
__device__ __half g_xh [(size_t)NN * NIN];    // x in fp16 (agg input)
__device__ __half g_hh [(size_t)NN * NIN];    // aggregated features, fp16
__device__ __half g_h1h[(size_t)NN * NHID];   // hidden layer, fp16
__device__ __half g_w0t[NHID * NIN];          // W0^T [n][k] fp16
__device__ __half g_w1t[NHID * NHID];         // W1^T [n][k] fp16

// ---------------- prep: deg init + dtype detect + x->fp16 + W transpose ----------------
__global__ void k_prep(const float* __restrict__ x, const void* __restrict__ ei,
                       const float* __restrict__ W0, const float* __restrict__ W1) {
    int i = blockIdx.x * blockDim.x + threadIdx.x;
    if (i < NN) g_deg[i] = 1;   // self loop
    if (i == 0) {
        const long long* p = (const long long*)ei;
        int ok = 1;
        #pragma unroll
        for (int t = 0; t < 16; t++) {
            long long v = p[t];
            ok &= (v >= 0 && v < NN) ? 1 : 0;
        }
        g_is64 = ok;
    }
    if (i < XV4) {
        float4 v = ((const float4*)x)[i];
        __half2 h0 = __floats2half2_rn(v.x, v.y);
        __half2 h1 = __floats2half2_rn(v.z, v.w);
        uint2 u;
        u.x = *(uint32_t*)&h0;
        u.y = *(uint32_t*)&h1;
        ((uint2*)g_xh)[i] = u;
    }
    if (i < NHID * NIN) {           // W0^T: i = n*128 + k
        int n = i >> 7, k = i & 127;
        g_w0t[i] = __float2half_rn(W0[k * NHID + n]);
    }
    if (i < NHID * NHID) {          // W1^T: i = n*256 + k
        int n = i >> 8, k = i & 255;
        g_w1t[i] = __float2half_rn(W1[k * NHID + n]);
    }
}

// ---------------- degree count (4 edges / thread) ----------------
__global__ void k_count(const void* __restrict__ ei) {
    int e4 = 4 * (blockIdx.x * blockDim.x + threadIdx.x);
    if (e4 >= EE) return;
    int c0, c1, c2, c3;
    if (g_is64) {
        const longlong2* p = (const longlong2*)((const long long*)ei + EE + e4);
        longlong2 a = p[0], b = p[1];
        c0 = (int)a.x; c1 = (int)a.y; c2 = (int)b.x; c3 = (int)b.y;
    } else {
        int4 v = *(const int4*)((const int*)ei + EE + e4);
        c0 = v.x; c1 = v.y; c2 = v.z; c3 = v.w;
    }
    atomicAdd(&g_deg[c0], 1);
    atomicAdd(&g_deg[c1], 1);
    atomicAdd(&g_deg[c2], 1);
    atomicAdd(&g_deg[c3], 1);
}

// ---------------- scan1: block-scan of (deg-1), also computes dinv ----------------
__global__ void k_scan1() {
    __shared__ int sh[SCAN_B];
    int gid = blockIdx.x * SCAN_B + threadIdx.x;
    int d = (gid < NN) ? g_deg[gid] : 1;
    int v = d - 1;
    if (gid < NN) g_dinv[gid] = rsqrtf((float)d);
    sh[threadIdx.x] = v;
    __syncthreads();
    for (int off = 1; off < SCAN_B; off <<= 1) {
        int t = (threadIdx.x >= off) ? sh[threadIdx.x - off] : 0;
        __syncthreads();
        sh[threadIdx.x] += t;
        __syncthreads();
    }
    if (gid < NN) g_ptr[gid] = sh[threadIdx.x] - v;   // exclusive within block
    if (threadIdx.x == SCAN_B - 1) g_bsum[blockIdx.x] = sh[SCAN_B - 1];
}

// scan3: each block sums its predecessor block-sums inline
__global__ void k_scan3() {
    __shared__ int sh[64];
    __shared__ int s_off;
    int t = threadIdx.x;
    if (t < 64) sh[t] = (t < SCAN_NB && t < blockIdx.x) ? g_bsum[t] : 0;
    __syncthreads();
    if (t == 0) {
        int acc = 0;
        #pragma unroll
        for (int b = 0; b < 64; b++) acc += sh[b];
        s_off = acc;
    }
    __syncthreads();
    int gid = blockIdx.x * SCAN_B + t;
    if (gid < NN) {
        int p = g_ptr[gid] + s_off;
        g_ptr[gid] = p;
        g_cur[gid] = p;
    }
    if (gid == 0) g_ptr[NN] = EE;
}

// ---------------- fill CSR (4 edges / thread) ----------------
__global__ void k_fill(const void* __restrict__ ei) {
    int e4 = 4 * (blockIdx.x * blockDim.x + threadIdx.x);
    if (e4 >= EE) return;
    int r0, r1, r2, r3, c0, c1, c2, c3;
    if (g_is64) {
        const longlong2* pr = (const longlong2*)((const long long*)ei + e4);
        const longlong2* pc = (const longlong2*)((const long long*)ei + EE + e4);
        longlong2 a = pr[0], b = pr[1], c = pc[0], d = pc[1];
        r0 = (int)a.x; r1 = (int)a.y; r2 = (int)b.x; r3 = (int)b.y;
        c0 = (int)c.x; c1 = (int)c.y; c2 = (int)d.x; c3 = (int)d.y;
    } else {
        int4 a = *(const int4*)((const int*)ei + e4);
        int4 b = *(const int4*)((const int*)ei + EE + e4);
        r0 = a.x; r1 = a.y; r2 = a.z; r3 = a.w;
        c0 = b.x; c1 = b.y; c2 = b.z; c3 = b.w;
    }
    g_src[atomicAdd(&g_cur[c0], 1)] = r0;
    g_src[atomicAdd(&g_cur[c1], 1)] = r1;
    g_src[atomicAdd(&g_cur[c2], 1)] = r2;
    g_src[atomicAdd(&g_cur[c3], 1)] = r3;
}

// ---------------- aggregation: warp per target node, fp16 in/out ----------------
__global__ void __launch_bounds__(256) k_agg() {
    int w = (blockIdx.x * blockDim.x + threadIdx.x) >> 5;
    int lane = threadIdx.x & 31;
    if (w >= NN) return;
    float di = g_dinv[w];
    const uint2* __restrict__ xh = (const uint2*)g_xh;   // 32 uint2 per row

    uint2 raw = xh[(size_t)w * 32 + lane];               // self loop
    float2 s0 = __half22float2(*(const __half2*)&raw.x);
    float2 s1 = __half22float2(*(const __half2*)&raw.y);
    float4 a;
    a.x = di * s0.x; a.y = di * s0.y; a.z = di * s1.x; a.w = di * s1.y;

    int s = g_ptr[w], e = g_ptr[w + 1];
    #pragma unroll 2
    for (int k = s; k < e; k++) {
        int   j  = __ldg(&g_src[k]);
        float wj = __ldg(&g_dinv[j]);
        uint2 r  = xh[(size_t)j * 32 + lane];
        float2 v0 = __half22float2(*(const __half2*)&r.x);
        float2 v1 = __half22float2(*(const __half2*)&r.y);
        a.x = fmaf(wj, v0.x, a.x);
        a.y = fmaf(wj, v0.y, a.y);
        a.z = fmaf(wj, v1.x, a.z);
        a.w = fmaf(wj, v1.y, a.w);
    }
    a.x *= di; a.y *= di; a.z *= di; a.w *= di;
    __half2 o0 = __floats2half2_rn(a.x, a.y);
    __half2 o1 = __floats2half2_rn(a.z, a.w);
    uint2 u;
    u.x = *(uint32_t*)&o0;
    u.y = *(uint32_t*)&o1;
    ((uint2*)g_hh)[(size_t)w * 32 + lane] = u;
}

// ---------------- FP16 tensor-core GEMM + ReLU, cp.async + ldmatrix ----------------
// Block tile 128x128, K-slab 64, 8 warps (2M x 4N), warp tile 64x32.
#define AST 36                      // smem row stride in words; 144B, 16B-aligned
#define SLAB_W (128 * AST)          // words per slab buffer
#define SMEM_GEMM (4 * SLAB_W * 4)  // A0,A1,B0,B1 in bytes (73728)

__device__ __forceinline__ void cp16(uint32_t dst_smem, const void* src, int sz) {
    asm volatile("cp.async.cg.shared.global [%0], [%1], 16, %2;\n"
                 :: "r"(dst_smem), "l"(src), "r"(sz));
}
__device__ __forceinline__ void cp_commit() {
    asm volatile("cp.async.commit_group;\n");
}
template<int N>
__device__ __forceinline__ void cp_wait() {
    asm volatile("cp.async.wait_group %0;\n" :: "n"(N));
}

__device__ __forceinline__ void ldsm4(uint32_t& r0, uint32_t& r1, uint32_t& r2,
                                      uint32_t& r3, uint32_t addr) {
    asm volatile("ldmatrix.sync.aligned.m8n8.x4.shared.b16 {%0,%1,%2,%3}, [%4];"
                 : "=r"(r0), "=r"(r1), "=r"(r2), "=r"(r3) : "r"(addr));
}

__device__ __forceinline__ void mma_fp16(float& d0, float& d1, float& d2, float& d3,
                                         uint32_t a0, uint32_t a1, uint32_t a2, uint32_t a3,
                                         uint32_t b0, uint32_t b1) {
    asm volatile(
        "mma.sync.aligned.m16n8k16.row.col.f32.f16.f16.f32 "
        "{%0,%1,%2,%3}, {%4,%5,%6,%7}, {%8,%9}, {%0,%1,%2,%3};"
        : "+f"(d0), "+f"(d1), "+f"(d2), "+f"(d3)
        : "r"(a0), "r"(a1), "r"(a2), "r"(a3), "r"(b0), "r"(b1));
}

// LAYER 1: A = g_hh (K=128), WT = g_w0t, C = g_h1h (fp16)
// LAYER 2: A = g_h1h (K=256), WT = g_w1t, C = Cout (fp32)
template<int K, int LAYER>
__global__ void __launch_bounds__(256) gemm_fp16(float* __restrict__ Cout, int M) {
    const __half* __restrict__ A  = (LAYER == 1) ? g_hh : g_h1h;
    const __half* __restrict__ WT = (LAYER == 1) ? g_w0t : g_w1t;

    extern __shared__ uint32_t smem[];
    uint32_t* Abuf[2] = { smem,             smem + SLAB_W };
    uint32_t* Bbuf[2] = { smem + 2*SLAB_W,  smem + 3*SLAB_W };
    uint32_t smem32 = (uint32_t)__cvta_generic_to_shared(smem);

    int tid  = threadIdx.x;
    int lane = tid & 31;
    int wid  = tid >> 5;
    int wM = (wid >> 2) * 64;
    int wN = (wid & 3) * 32;
    int r4 = lane >> 2;
    int c4 = lane & 3;

    int brow = blockIdx.x * 128;
    int bcol = blockIdx.y * 128;

    // ldmatrix lane-offsets (bytes, relative to slab base)
    // A (per mt): row = wM + mt*16 + (lane&15), k-half = lane>>4 (4 words)
    uint32_t a_loff[4];
    #pragma unroll
    for (int mt = 0; mt < 4; mt++)
        a_loff[mt] = (((uint32_t)(wM + mt * 16 + (lane & 15))) * AST + (lane >> 4) * 4) * 4;
    // B (per nt-pair p): group g = lane>>3: nt = 2p + (g>>1), khalf = g&1, j = lane&7
    uint32_t b_loff[2];
    #pragma unroll
    for (int p = 0; p < 2; p++) {
        int g  = lane >> 3;
        int nt = 2 * p + (g >> 1);
        int kh = g & 1;
        int j  = lane & 7;
        b_loff[p] = (((uint32_t)(wN + nt * 8 + j)) * AST + kh * 4) * 4;
    }

    // async load of one 64-k slab into buffer b (A: rows may be OOB -> zfill)
    auto load_slab = [&](int b, int k0) {
        uint32_t a_base = (uint32_t)__cvta_generic_to_shared(Abuf[b]);
        uint32_t b_base = (uint32_t)__cvta_generic_to_shared(Bbuf[b]);
        #pragma unroll
        for (int t = 0; t < 4; t++) {
            int idx = tid + t * 256;        // uint4 index, 8 per row
            int row = idx >> 3;
            int c   = idx & 7;
            int grow = brow + row;
            int ok = (grow < M);
            const __half* srcA = A + (size_t)(ok ? grow : 0) * K + k0 + c * 8;
            cp16(a_base + (row * AST + c * 4) * 4, srcA, ok ? 16 : 0);
            const __half* srcB = WT + (size_t)(bcol + row) * K + k0 + c * 8;
            cp16(b_base + (row * AST + c * 4) * 4, srcB, 16);
        }
        cp_commit();
    };

    float acc[4][4][4];
    #pragma unroll
    for (int mt = 0; mt < 4; mt++)
        #pragma unroll
        for (int nt = 0; nt < 4; nt++)
            #pragma unroll
            for (int r = 0; r < 4; r++) acc[mt][nt][r] = 0.f;

    const int NSLAB = K / 64;
    load_slab(0, 0);

    #pragma unroll
    for (int i = 0; i < NSLAB; i++) {
        if (i + 1 < NSLAB) {
            load_slab((i + 1) & 1, (i + 1) * 64);
            cp_wait<1>();
        } else {
            cp_wait<0>();
        }
        __syncthreads();

        uint32_t aS = smem32 + ((i & 1) ? SLAB_W * 4 : 0);
        uint32_t bS = smem32 + (2 + (i & 1)) * SLAB_W * 4;

        #pragma unroll
        for (int s = 0; s < 4; s++) {      // 4 x k16 steps; kw bytes = s*32
            uint32_t kb = (uint32_t)s * 32;
            uint32_t af[4][4];
            #pragma unroll
            for (int mt = 0; mt < 4; mt++)
                ldsm4(af[mt][0], af[mt][1], af[mt][2], af[mt][3],
                      aS + a_loff[mt] + kb);
            uint32_t bf[4][2];
            ldsm4(bf[0][0], bf[0][1], bf[1][0], bf[1][1], bS + b_loff[0] + kb);
            ldsm4(bf[2][0], bf[2][1], bf[3][0], bf[3][1], bS + b_loff[1] + kb);
            #pragma unroll
            for (int mt = 0; mt < 4; mt++)
                #pragma unroll
                for (int nt = 0; nt < 4; nt++)
                    mma_fp16(acc[mt][nt][0], acc[mt][nt][1], acc[mt][nt][2], acc[mt][nt][3],
                             af[mt][0], af[mt][1], af[mt][2], af[mt][3],
                             bf[nt][0], bf[nt][1]);
        }
        __syncthreads();   // all reads of this buffer done before it is re-filled
    }

    // epilogue
    #pragma unroll
    for (int mt = 0; mt < 4; mt++) {
        int row0 = brow + wM + mt * 16 + r4;
        #pragma unroll
        for (int nt = 0; nt < 4; nt++) {
            int col = bcol + wN + nt * 8 + c4 * 2;
            if (LAYER == 1) {
                if (row0 < M) {
                    __half2 h = __floats2half2_rn(fmaxf(acc[mt][nt][0], 0.f),
                                                  fmaxf(acc[mt][nt][1], 0.f));
                    *(__half2*)(g_h1h + (size_t)row0 * NHID + col) = h;
                }
                if (row0 + 8 < M) {
                    __half2 h = __floats2half2_rn(fmaxf(acc[mt][nt][2], 0.f),
                                                  fmaxf(acc[mt][nt][3], 0.f));
                    *(__half2*)(g_h1h + (size_t)(row0 + 8) * NHID + col) = h;
                }
            } else {
                if (row0 < M) {
                    float2 v;
                    v.x = fmaxf(acc[mt][nt][0], 0.f);
                    v.y = fmaxf(acc[mt][nt][1], 0.f);
                    *(float2*)(Cout + (size_t)row0 * NHID + col) = v;
                }
                if (row0 + 8 < M) {
                    float2 v;
                    v.x = fmaxf(acc[mt][nt][2], 0.f);
                    v.y = fmaxf(acc[mt][nt][3], 0.f);
                    *(float2*)(Cout + (size_t)(row0 + 8) * NHID + col) = v;
                }
            }
        }
    }
}

extern "C" void kernel_launch(void* const* d_in, const int* in_sizes, int n_in,
                              void* d_out, int out_size) {
    const float* x  = nullptr;
    const float* W0 = nullptr;
    const float* W1 = nullptr;
    const void*  ei = nullptr;
    for (int i = 0; i < n_in; i++) {
        long long sz = in_sizes[i];
        if      (sz == (long long)NN * NIN)    x  = (const float*)d_in[i];
        else if (sz == (long long)NIN * NHID)  W0 = (const float*)d_in[i];
        else if (sz == (long long)NHID * NHID) W1 = (const float*)d_in[i];
        else if (sz == (long long)2 * EE)      ei = d_in[i];
    }

    cudaFuncSetAttribute(gemm_fp16<NIN, 1>,
                         cudaFuncAttributeMaxDynamicSharedMemorySize, SMEM_GEMM);
    cudaFuncSetAttribute(gemm_fp16<NHID, 2>,
                         cudaFuncAttributeMaxDynamicSharedMemorySize, SMEM_GEMM);

    k_prep <<<(XV4 + 255) / 256, 256>>>(x, ei, W0, W1);
    k_count<<<(EE / 4 + 255) / 256, 256>>>(ei);
    k_scan1<<<SCAN_NB, SCAN_B>>>();
    k_scan3<<<SCAN_NB, SCAN_B>>>();
    k_fill <<<(EE / 4 + 255) / 256, 256>>>(ei);

    k_agg<<<(NN * 32 + 255) / 256, 256>>>();

    dim3 gg((NN + 127) / 128, NHID / 128);
    gemm_fp16<NIN,  1><<<gg, 256, SMEM_GEMM>>>(nullptr, NN);        // g_hh @ W0 -> g_h1h
    gemm_fp16<NHID, 2><<<gg, 256, SMEM_GEMM>>>((float*)d_out, NN);  // g_h1h @ W1 -> out
}